// round 2
// baseline (speedup 1.0000x reference)
#include <cuda_runtime.h>
#include <cstdint>

#define HH 1024
#define WW 1024
#define CF 8
#define HWs (HH*WW)
#define BIGV 1e18f
#define L2E 1.4426950408889634f

typedef unsigned long long ull;

__device__ __forceinline__ ull pk(float a, float b) {
    ull r;
    asm("mov.b64 %0, {%1, %2};" : "=l"(r) : "f"(a), "f"(b));
    return r;
}
__device__ __forceinline__ void upk(ull v, float& a, float& b) {
    asm("mov.b64 {%0, %1}, %2;" : "=f"(a), "=f"(b) : "l"(v));
}
__device__ __forceinline__ ull fma2(ull a, ull b, ull c) {
    ull d;
    asm("fma.rn.f32x2 %0, %1, %2, %3;" : "=l"(d) : "l"(a), "l"(b), "l"(c));
    return d;
}
__device__ __forceinline__ ull add2(ull a, ull b) {
    ull d;
    asm("add.rn.f32x2 %0, %1, %2;" : "=l"(d) : "l"(a), "l"(b));
    return d;
}
__device__ __forceinline__ float ex2(float x) {
    float y;
    asm("ex2.approx.f32 %0, %1;" : "=f"(y) : "f"(x));
    return y;
}

// Tile: 64 wide x 8 high. Threads (32,8); thread tx handles pixels X0+tx and X0+tx+32
// (stride-32 pairing -> lane-consecutive LDS addresses, conflict-free).
// SMEM: 8 channels x 14 rows x 72 cols (x from X0-3 .. X0+68; cols 0..69 used).
__global__ __launch_bounds__(256, 2)
void bilateral_kernel(const float* __restrict__ in, float* __restrict__ out)
{
    __shared__ float smf[CF][14][72];
    const int tx = threadIdx.x, ty = threadIdx.y;
    const int X0 = blockIdx.x * 64;
    const int Y0 = blockIdx.y * 8;
    const int b  = blockIdx.z;
    const float* __restrict__ inb = in + (size_t)b * 18 * HWs;

    // ---- load filterable channels (+halo) into SMEM, sentinel for OOB ----
    const int tid = ty * 32 + tx;
    for (int i = tid; i < CF * 14 * 72; i += 256) {
        int c   = i / (14 * 72);
        int rem = i - c * (14 * 72);
        int r   = rem / 72;
        int col = rem - r * 72;
        int gy = Y0 - 3 + r;
        int gx = X0 - 3 + col;
        float v = BIGV;
        if ((unsigned)gx < WW && (unsigned)gy < HH)
            v = inb[c * HWs + gy * WW + gx];
        smf[c][r][col] = v;
    }
    __syncthreads();

    const int gx0 = X0 + tx, gx1 = gx0 + 32;
    const int gy  = Y0 + ty;

    // ---- per-pixel precompute: rp' = -(p^2)*log2(e), u = -2 rp' f, v = sum rp' f^2 ----
    ull rpp[CF], up[CF];
    float v0 = 0.f, v1 = 0.f;
    const float* __restrict__ pb = inb + 8 * HWs + gy * WW;
    #pragma unroll
    for (int c = 0; c < CF; c++) {
        float p0 = pb[c * HWs + gx0];
        float p1 = pb[c * HWs + gx1];
        float r0 = -(p0 * p0) * L2E;
        float r1 = -(p1 * p1) * L2E;
        float f0 = smf[c][ty + 3][tx + 3];
        float f1 = smf[c][ty + 3][tx + 35];
        v0 = fmaf(r0 * f0, f0, v0);
        v1 = fmaf(r1 * f1, f1, v1);
        rpp[c] = pk(r0, r1);
        up[c]  = pk(-2.f * r0 * f0, -2.f * r1 * f1);
    }
    float sxa = pb[8 * HWs + gx0], sxb = pb[8 * HWs + gx1];
    float sya = pb[9 * HWs + gx0], syb = pb[9 * HWs + gx1];
    const ull sxp = pk(-(sxa * sxa) * L2E, -(sxb * sxb) * L2E);
    const ull syp = pk(-(sya * sya) * L2E, -(syb * syb) * L2E);
    const ull vp  = pk(v0, v1);

    const ull d1 = pk(1.f, 1.f);
    const ull d4 = pk(4.f, 4.f);
    const ull d9 = pk(9.f, 9.f);

    ull acc0 = 0ULL, acc1 = 0ULL, acc2 = 0ULL, wsp = 0ULL;  // packed {0,0}

    // ---- main loop: dy rolled (keeps code in L0 I$), dx & c unrolled ----
    for (int dy = 0; dy < 7; dy++) {
        float dyf = (float)((dy - 3) * (dy - 3));
        ull rb = fma2(syp, pk(dyf, dyf), vp);
        const float* __restrict__ rowp = &smf[0][ty + dy][tx];
        #pragma unroll
        for (int dx = 0; dx < 7; dx++) {
            ull lw;
            if      (dx == 3)             lw = rb;
            else if (dx == 2 || dx == 4)  lw = fma2(sxp, d1, rb);
            else if (dx == 1 || dx == 5)  lw = fma2(sxp, d4, rb);
            else                          lw = fma2(sxp, d9, rb);

            ull fn0 = 0, fn1 = 0, fn2 = 0;
            #pragma unroll
            for (int c = 0; c < CF; c++) {
                const float* p = rowp + c * (14 * 72) + dx;
                ull fnp = pk(p[0], p[32]);
                ull s   = fma2(rpp[c], fnp, up[c]);
                lw = fma2(s, fnp, lw);
                if (c == 0) fn0 = fnp;
                else if (c == 1) fn1 = fnp;
                else if (c == 2) fn2 = fnp;
            }
            float l0, l1;
            upk(lw, l0, l1);
            ull wp2 = pk(ex2(l0), ex2(l1));
            acc0 = fma2(wp2, fn0, acc0);
            acc1 = fma2(wp2, fn1, acc1);
            acc2 = fma2(wp2, fn2, acc2);
            wsp  = add2(wsp, wp2);
        }
    }

    float ws0, ws1, a0, a1;
    upk(wsp, ws0, ws1);
    float* __restrict__ ob = out + (size_t)b * 3 * HWs + gy * WW;
    upk(acc0, a0, a1); ob[gx0]           = a0 / ws0; ob[gx1]           = a1 / ws1;
    upk(acc1, a0, a1); ob[HWs + gx0]     = a0 / ws0; ob[HWs + gx1]     = a1 / ws1;
    upk(acc2, a0, a1); ob[2 * HWs + gx0] = a0 / ws0; ob[2 * HWs + gx1] = a1 / ws1;
}

extern "C" void kernel_launch(void* const* d_in, const int* in_sizes, int n_in,
                              void* d_out, int out_size) {
    const float* in = (const float*)d_in[0];
    float* out = (float*)d_out;
    dim3 grid(WW / 64, HH / 8, 2);
    dim3 block(32, 8);
    bilateral_kernel<<<grid, block>>>(in, out);
}